// round 5
// baseline (speedup 1.0000x reference)
#include <cuda_runtime.h>

#define Bn 64
#define Tn 512
#define Ln 48
#define STARTL 46
#define ENDL 47
#define LOG2E_F 1.4426950408889634f
#define LN2_F   0.6931471805599453f

__device__ __forceinline__ float ex2f_(float x){float r;asm("ex2.approx.f32 %0,%1;":"=f"(r):"f"(x));return r;}
__device__ __forceinline__ float lg2f_(float x){float r;asm("lg2.approx.f32 %0,%1;":"=f"(r):"f"(x));return r;}
__device__ __forceinline__ float rcpf_(float x){float r;asm("rcp.approx.f32 %0,%1;":"=f"(r):"f"(x));return r;}
__device__ __forceinline__ unsigned long long pack2_(float a,float b){
    unsigned long long d;asm("mov.b64 %0,{%1,%2};":"=l"(d):"f"(a),"f"(b));return d;}
__device__ __forceinline__ void unpack2_(unsigned long long d,float&a,float&b){
    asm("mov.b64 {%0,%1},%2;":"=f"(a),"=f"(b):"l"(d));}
__device__ __forceinline__ void fma2_(unsigned long long&d,unsigned long long a,unsigned long long b){
    asm("fma.rn.f32x2 %0,%1,%2,%0;":"+l"(d):"l"(a),"l"(b));}
__device__ __forceinline__ unsigned long long mul2_(unsigned long long a,unsigned long long b){
    unsigned long long d;asm("mul.rn.f32x2 %0,%1,%2;":"=l"(d):"l"(a),"l"(b));return d;}
__device__ __forceinline__ unsigned long long add2_(unsigned long long a,unsigned long long b){
    unsigned long long d;asm("add.rn.f32x2 %0,%1,%2;":"=l"(d):"l"(a),"l"(b));return d;}

// dynamic smem layout (floats):
//   s_sh  : (Tn+1)*Ln   scores for this batch + one zero pad row
//   h_sh  : 2*Ln        double-buffered h = g * exp(s_t)
//   m_sh  : Tn (ints)   mask row
//   t0_sh : Ln          trans row 0 (for gold-energy)
//   ps    : 64          partial sums
//   misc  : 8           [0]=fs[END], [1](int)=gold-is-int64 flag
#define SM_FLOATS (((Tn+1)*Ln) + 2*Ln + Tn + Ln + 64 + 8)
#define SM_BYTES  (SM_FLOATS*4)

__global__ void zero_out_k(float* o){ o[0] = 0.0f; }

__global__ __launch_bounds__(64,1)
void crf_main(const float* __restrict__ scores,
              const int*   __restrict__ gold_i,   // int32 view (may really be int64)
              const int*   __restrict__ mask,
              const float* __restrict__ trans,
              float*       __restrict__ out)
{
    extern __shared__ float sm[];
    float* s_sh  = sm;
    float* h_sh  = sm + (Tn+1)*Ln;
    int*   m_sh  = (int*)(h_sh + 2*Ln);
    float* t0_sh = (float*)(m_sh + Tn);
    float* ps    = t0_sh + Ln;
    float* misc  = ps + 64;

    const int tid = threadIdx.x;
    const int b   = blockIdx.x;

    // ---- stage scores[b,:,:] into shared (float4) ----
    {
        const float4* src = (const float4*)(scores + (size_t)b * Tn * Ln);
        float4* dst = (float4*)s_sh;
        #pragma unroll 4
        for (int i = tid; i < (Tn*Ln)/4; i += 64) dst[i] = src[i];
        if (tid < 12) ((float4*)(s_sh + Tn*Ln))[tid] = make_float4(0.f,0.f,0.f,0.f);
        const int4* msrc = (const int4*)(mask + b * Tn);
        int4* mdst = (int4*)m_sh;
        for (int i = tid; i < Tn/4; i += 64) mdst[i] = msrc[i];
        if (tid < Ln) t0_sh[tid] = trans[tid];           // trans row 0
    }
    // ---- detect gold dtype (int64 elements have zero hi-words; values < 48) ----
    if (tid == 0){
        int f = 1;
        #pragma unroll
        for (int j = 0; j < 32; j++) f &= (gold_i[2*j+1] == 0);
        ((int*)misc)[1] = f;
    }

    // ---- per-thread W column (exp of transitions), packed f32x2 ----
    const int yy = (tid < Ln) ? tid : 0;
    unsigned long long w[24];
    #pragma unroll
    for (int j = 0; j < 24; j++){
        float wa = ex2f_(trans[(2*j  )*Ln + yy] * LOG2E_F);
        float wb = ex2f_(trans[(2*j+1)*Ln + yy] * LOG2E_F);
        w[j] = pack2_(wa, wb);
    }

    __syncthreads();

    // ---- init: fs0[y] = trans[START,y]  ->  g = exp(fs0), h = g*exp(s_0) ----
    float g_prev = 0.0f;
    if (tid < Ln){
        float ts = trans[STARTL*Ln + tid];
        g_prev   = ex2f_(ts * LOG2E_F);
        h_sh[tid]= ex2f_((ts + s_sh[tid]) * LOG2E_F);
    }
    __syncthreads();

    // ---- main recurrence: one barrier per step ----
    float C2 = 0.0f;   // accumulated log2 scale
    #pragma unroll 2
    for (int t = 0; t < Tn; t++){
        const float* hc = h_sh + ((t & 1) * Ln);
        float*       hn = h_sh + (((t & 1) ^ 1) * Ln);
        if (tid < Ln){
            const ulonglong2* hp = (const ulonglong2*)hc;
            ulonglong2 v[12];
            #pragma unroll
            for (int j = 0; j < 12; j++) v[j] = hp[j];

            unsigned long long a0 = mul2_(v[0].x, w[0]);
            unsigned long long a1 = mul2_(v[0].y, w[1]);
            unsigned long long a2 = mul2_(v[1].x, w[2]);
            unsigned long long a3 = mul2_(v[1].y, w[3]);
            #pragma unroll
            for (int p = 4; p < 24; p += 4){
                fma2_(a0, v[(p>>1)  ].x, w[p  ]);
                fma2_(a1, v[(p>>1)  ].y, w[p+1]);
                fma2_(a2, v[(p>>1)+1].x, w[p+2]);
                fma2_(a3, v[(p>>1)+1].y, w[p+3]);
            }
            unsigned long long s01 = add2_(a0, a1);
            unsigned long long s23 = add2_(a2, a3);
            unsigned long long sal = add2_(s01, s23);
            float lo, hi; unpack2_(sal, lo, hi);
            float gp = lo + hi;                       // g'[y] (unnormalized)

            float h0, h0b; unpack2_(v[0].x, h0, h0b); // h[0] = renorm scalar (> 0)
            float r = rcpf_(h0);
            C2 += lg2f_(h0);

            float gsel = m_sh[t] ? gp : g_prev;       // mask: freeze fs
            gsel *= r;                                // renormalize (C2 compensates)
            g_prev = gsel;

            float e = ex2f_(s_sh[(t+1)*Ln + tid] * LOG2E_F);  // next emission (0-pad at T)
            hn[tid] = gsel * e;
        }
        __syncthreads();
    }

    // ---- forward score: fs[END] = (C2 + log2 g[END]) * ln2 ----
    if (tid == ENDL) misc[0] = (C2 + lg2f_(g_prev)) * LN2_F;

    // ---- gold path energy (replicates reference's flat-index gather: crf[t,b,0,g]) ----
    const int is64 = ((int*)misc)[1];
    float p = 0.0f;
    for (int tt = tid; tt < Tn; tt += 64){
        int idx = b*Tn + tt;
        int g   = is64 ? gold_i[2*idx] : gold_i[idx];
        float mm = (float)m_sh[tt];
        p += mm * (s_sh[tt*Ln] + t0_sh[g]);
    }
    ps[tid] = p;
    __syncthreads();

    if (tid == 0){
        float tot = 0.0f;
        #pragma unroll
        for (int i = 0; i < 64; i++) tot += ps[i];
        float res = (misc[0] - tot - t0_sh[STARTL]) * (1.0f / (float)Bn);
        atomicAdd(out, res);
    }
}

extern "C" void kernel_launch(void* const* d_in, const int* in_sizes, int n_in,
                              void* d_out, int out_size)
{
    const float* scores = (const float*)d_in[0];
    const int*   gold   = (const int*)  d_in[1];
    const int*   mask   = (const int*)  d_in[2];
    const float* trans  = (const float*)d_in[3];
    float* out = (float*)d_out;

    cudaFuncSetAttribute(crf_main, cudaFuncAttributeMaxDynamicSharedMemorySize, SM_BYTES);

    zero_out_k<<<1, 1>>>(out);
    crf_main<<<Bn, 64, SM_BYTES>>>(scores, gold, mask, trans, out);
}

// round 6
// speedup vs baseline: 1.2975x; 1.2975x over previous
#include <cuda_runtime.h>

#define Bn 64
#define Tn 512
#define Ln 48
#define STARTL 46
#define ENDL 47
#define PFD 4
#define LOG2E_F 1.4426950408889634f
#define LN2_F   0.6931471805599453f

__device__ __forceinline__ float ex2f_(float x){float r;asm("ex2.approx.f32 %0,%1;":"=f"(r):"f"(x));return r;}
__device__ __forceinline__ float lg2f_(float x){float r;asm("lg2.approx.f32 %0,%1;":"=f"(r):"f"(x));return r;}
__device__ __forceinline__ unsigned long long pack2_(float a,float b){
    unsigned long long d;asm("mov.b64 %0,{%1,%2};":"=l"(d):"f"(a),"f"(b));return d;}
__device__ __forceinline__ void unpack2_(unsigned long long d,float&a,float&b){
    asm("mov.b64 {%0,%1},%2;":"=f"(a),"=f"(b):"l"(d));}
__device__ __forceinline__ void fma2_(unsigned long long&d,unsigned long long a,unsigned long long b){
    asm("fma.rn.f32x2 %0,%1,%2,%0;":"+l"(d):"l"(a),"l"(b));}
__device__ __forceinline__ unsigned long long mul2_(unsigned long long a,unsigned long long b){
    unsigned long long d;asm("mul.rn.f32x2 %0,%1,%2;":"=l"(d):"l"(a),"l"(b));return d;}
__device__ __forceinline__ unsigned long long add2_(unsigned long long a,unsigned long long b){
    unsigned long long d;asm("add.rn.f32x2 %0,%1,%2;":"=l"(d):"l"(a),"l"(b));return d;}

__global__ void zero_out_k(float* o){ o[0] = 0.0f; }

// One step of the scaled forward recurrence.
// Consumes h in h_sh[CUR..CUR+48), writes h_sh[NXT..NXT+48).
// PFV = s[T_+1] (register prefetch, reloaded 4 steps ahead, clamped).
// Renorm by exact power of two derived from h[0]'s exponent: no MUFU on path.
#define STEP(T_, CUR, NXT, PFV) do {                                           \
    const ulonglong2* hp_ = (const ulonglong2*)(h_sh + (CUR));                 \
    ulonglong2 v[12];                                                          \
    _Pragma("unroll") for (int j = 0; j < 12; j++) v[j] = hp_[j];              \
    const int m_t_ = m_sh[T_];                                                 \
    float e_ = ex2f_((PFV) * LOG2E_F);                                         \
    { int ri_ = (T_) + 1 + PFD; ri_ = ri_ < Tn-1 ? ri_ : Tn-1;                 \
      PFV = sp[ri_ * Ln]; }                                                    \
    float h0_, hxx_; unpack2_(v[0].x, h0_, hxx_);                              \
    unsigned ue_ = __float_as_uint(h0_) >> 23;                                 \
    C2i += (int)ue_;                                                           \
    float scale_ = __uint_as_float((254u - ue_) << 23);                        \
    float se_ = scale_ * e_;                                                   \
    unsigned long long a0 = mul2_(v[0].x, w[0]);                               \
    unsigned long long a1 = mul2_(v[0].y, w[1]);                               \
    unsigned long long a2 = mul2_(v[1].x, w[2]);                               \
    unsigned long long a3 = mul2_(v[1].y, w[3]);                               \
    _Pragma("unroll") for (int p = 4; p < 24; p += 4){                         \
        fma2_(a0, v[(p>>1)    ].x, w[p  ]);                                    \
        fma2_(a1, v[(p>>1)    ].y, w[p+1]);                                    \
        fma2_(a2, v[(p>>1) + 1].x, w[p+2]);                                    \
        fma2_(a3, v[(p>>1) + 1].y, w[p+3]);                                    \
    }                                                                          \
    unsigned long long s01_ = add2_(a0, a1);                                   \
    unsigned long long s23_ = add2_(a2, a3);                                   \
    unsigned long long sal_ = add2_(s01_, s23_);                               \
    float lo_, hi_; unpack2_(sal_, lo_, hi_);                                  \
    float gp_ = lo_ + hi_;                                                     \
    float gsel_ = m_t_ ? gp_ : g_prev;                                         \
    g_prev = gsel_ * scale_;                                                   \
    if (tid < Ln) h_sh[(NXT) + tid] = gsel_ * se_;                             \
    __syncthreads();                                                           \
} while(0)

__global__ __launch_bounds__(64,1)
void crf_main(const float* __restrict__ scores,
              const int*   __restrict__ gold_i,   // int32 view (may really be int64)
              const int*   __restrict__ mask,
              const float* __restrict__ trans,
              float*       __restrict__ out)
{
    __shared__ float h_sh[2*Ln];        // double-buffered h = g * exp(s_t)
    __shared__ float t0_sh[Ln];         // trans row 0 (gold-energy gather)
    __shared__ int   m_sh[Tn];          // mask row
    __shared__ float ps[64];            // partial sums
    __shared__ float miscF[4];
    __shared__ int   miscI[4];

    const int tid = threadIdx.x;
    const int b   = blockIdx.x;

    // ---- stage mask row (2 KB) + trans row 0 ----
    {
        const int4* msrc = (const int4*)(mask + b * Tn);
        #pragma unroll
        for (int i = tid; i < Tn/4; i += 64) ((int4*)m_sh)[i] = msrc[i];
    }
    if (tid < Ln) t0_sh[tid] = trans[tid];
    // gold dtype detect (int64 hi-words are zero since labels < 48)
    if (tid == 0){
        int f = 1;
        #pragma unroll
        for (int j = 0; j < 32; j++) f &= (gold_i[2*j+1] == 0);
        miscI[0] = f;
    }

    // ---- per-thread W column (exp of transitions), packed f32x2 ----
    const int yy = (tid < Ln) ? tid : 0;
    unsigned long long w[24];
    #pragma unroll
    for (int j = 0; j < 24; j++){
        float wa = ex2f_(trans[(2*j  )*Ln + yy] * LOG2E_F);
        float wb = ex2f_(trans[(2*j+1)*Ln + yy] * LOG2E_F);
        w[j] = pack2_(wa, wb);
    }

    // ---- emission stream: thread y reads scores[b, t, y] (reg prefetch, depth 4) ----
    const float* sp = scores + (size_t)b * Tn * Ln + yy;
    float pf0 = sp[1*Ln], pf1 = sp[2*Ln], pf2 = sp[3*Ln], pf3 = sp[4*Ln];

    // ---- init: fs0[y] = trans[START,y]  ->  g = exp(fs0), h0 = g * exp(s_0) ----
    float ts = trans[STARTL*Ln + yy];
    float g_prev = ex2f_(ts * LOG2E_F);
    if (tid < Ln) h_sh[tid] = ex2f_((ts + sp[0]) * LOG2E_F);
    __syncthreads();

    // ---- main recurrence ----
    int C2i = 0;   // accumulated biased exponents of renorm scales
    for (int t = 0; t < Tn; t += 4){
        STEP(t  , 0,  Ln, pf0);
        STEP(t+1, Ln, 0,  pf1);
        STEP(t+2, 0,  Ln, pf2);
        STEP(t+3, Ln, 0,  pf3);
    }

    // ---- forward score: fs[END] = ((C2i - 127*Tn) + log2 g[END]) * ln2 ----
    if (tid == ENDL)
        miscF[0] = ((float)(C2i - 127*Tn) + lg2f_(g_prev)) * LN2_F;

    // ---- gold path energy: sum_t mask[t] * (scores[b,t,0] + trans[0, gold[b,t]]) ----
    const int is64 = miscI[0];
    const float* sb0 = scores + (size_t)b * Tn * Ln;
    float p = 0.0f;
    #pragma unroll 4
    for (int tt = tid; tt < Tn; tt += 64){
        int idx = b*Tn + tt;
        int g   = is64 ? gold_i[2*idx] : gold_i[idx];
        p += (float)m_sh[tt] * (sb0[tt*Ln] + t0_sh[g]);
    }
    ps[tid] = p;
    __syncthreads();

    if (tid == 0){
        float tot = 0.0f;
        #pragma unroll
        for (int i = 0; i < 64; i++) tot += ps[i];
        float res = (miscF[0] - tot - t0_sh[STARTL]) * (1.0f / (float)Bn);
        atomicAdd(out, res);
    }
}

extern "C" void kernel_launch(void* const* d_in, const int* in_sizes, int n_in,
                              void* d_out, int out_size)
{
    const float* scores = (const float*)d_in[0];
    const int*   gold   = (const int*)  d_in[1];
    const int*   mask   = (const int*)  d_in[2];
    const float* trans  = (const float*)d_in[3];
    float* out = (float*)d_out;

    zero_out_k<<<1, 1>>>(out);
    crf_main<<<Bn, 64>>>(scores, gold, mask, trans, out);
}

// round 7
// speedup vs baseline: 2.4460x; 1.8851x over previous
#include <cuda_runtime.h>

#define Bn 64
#define Tn 512
#define Ln 48
#define HALF 256
#define STARTL 46
#define ENDL 47
#define PFD 4
#define LOG2E_F 1.4426950408889634f
#define LN2_F   0.6931471805599453f

__device__ __forceinline__ float ex2f_(float x){float r;asm("ex2.approx.f32 %0,%1;":"=f"(r):"f"(x));return r;}
__device__ __forceinline__ float lg2f_(float x){float r;asm("lg2.approx.f32 %0,%1;":"=f"(r):"f"(x));return r;}
__device__ __forceinline__ unsigned long long pack2_(float a,float b){
    unsigned long long d;asm("mov.b64 %0,{%1,%2};":"=l"(d):"f"(a),"f"(b));return d;}
__device__ __forceinline__ void unpack2_(unsigned long long d,float&a,float&b){
    asm("mov.b64 {%0,%1},%2;":"=f"(a),"=f"(b):"l"(d));}
__device__ __forceinline__ void fma2_(unsigned long long&d,unsigned long long a,unsigned long long b){
    asm("fma.rn.f32x2 %0,%1,%2,%0;":"+l"(d):"l"(a),"l"(b));}
__device__ __forceinline__ unsigned long long mul2_(unsigned long long a,unsigned long long b){
    unsigned long long d;asm("mul.rn.f32x2 %0,%1,%2;":"=l"(d):"l"(a),"l"(b));return d;}
__device__ __forceinline__ unsigned long long add2_(unsigned long long a,unsigned long long b){
    unsigned long long d;asm("add.rn.f32x2 %0,%1,%2;":"=l"(d):"l"(a),"l"(b));return d;}

// cross-kernel scratch: [dir][batch][48 used of 64]
__device__ float g_scr[2][Bn][64];
__device__ int   c_scr[2][Bn];

__global__ void zero_out_k(float* o){ o[0] = 0.0f; }

// shared matvec body: v (12 x ulonglong2 from smem) dot per-thread w[24] -> gp_
#define MATVEC(GPOUT) \
    unsigned long long a0 = mul2_(v[0].x, w[0]);                               \
    unsigned long long a1 = mul2_(v[0].y, w[1]);                               \
    unsigned long long a2 = mul2_(v[1].x, w[2]);                               \
    unsigned long long a3 = mul2_(v[1].y, w[3]);                               \
    _Pragma("unroll") for (int p = 4; p < 24; p += 4){                         \
        fma2_(a0, v[(p>>1)    ].x, w[p  ]);                                    \
        fma2_(a1, v[(p>>1)    ].y, w[p+1]);                                    \
        fma2_(a2, v[(p>>1) + 1].x, w[p+2]);                                    \
        fma2_(a3, v[(p>>1) + 1].y, w[p+3]);                                    \
    }                                                                          \
    unsigned long long s01_ = add2_(a0, a1);                                   \
    unsigned long long s23_ = add2_(a2, a3);                                   \
    unsigned long long sal_ = add2_(s01_, s23_);                               \
    float lo_, hi_; unpack2_(sal_, lo_, hi_);                                  \
    float GPOUT = lo_ + hi_;

// forward step: h' = select(W^T h, g_prev) * scale * e_{t+1}
#define STEPF(T_, CUR, NXT, PFV) do {                                          \
    const ulonglong2* hp_ = (const ulonglong2*)(h_sh + (CUR));                 \
    ulonglong2 v[12];                                                          \
    _Pragma("unroll") for (int j = 0; j < 12; j++) v[j] = hp_[j];              \
    const int m_t_ = m_sh[T_];                                                 \
    float e_ = ex2f_((PFV) * LOG2E_F);                                         \
    PFV = sp[((T_) + 1 + PFD) * Ln];                                           \
    float h0_, hxx_; unpack2_(v[0].x, h0_, hxx_);                              \
    unsigned ue_ = __float_as_uint(h0_) >> 23;                                 \
    C2i += (int)ue_;                                                           \
    float scale_ = __uint_as_float((254u - ue_) << 23);                        \
    float se_ = scale_ * e_;                                                   \
    MATVEC(gp_)                                                                \
    float gsel_ = m_t_ ? gp_ : g_prev;                                         \
    g_prev = gsel_ * scale_;                                                   \
    if (tid < Ln) h_sh[(NXT) + tid] = gsel_ * se_;                             \
    __syncthreads();                                                           \
} while(0)

// backward step: beta' = select((W beta) * e_t, beta_old) * scale
#define STEPB(T_, CUR, NXT, PFV) do {                                          \
    const ulonglong2* hp_ = (const ulonglong2*)(h_sh + (CUR));                 \
    ulonglong2 v[12];                                                          \
    _Pragma("unroll") for (int j = 0; j < 12; j++) v[j] = hp_[j];              \
    const int m_t_ = m_sh[T_];                                                 \
    float e_ = ex2f_((PFV) * LOG2E_F);                                         \
    PFV = sp[((T_) - PFD) * Ln];                                               \
    float h0_, hxx_; unpack2_(v[0].x, h0_, hxx_);                              \
    unsigned ue_ = __float_as_uint(h0_) >> 23;                                 \
    C2i += (int)ue_;                                                           \
    float scale_ = __uint_as_float((254u - ue_) << 23);                        \
    MATVEC(gp_)                                                                \
    float cand_ = gp_ * e_;                                                    \
    float bsel_ = m_t_ ? cand_ : bp;                                           \
    bp = bsel_ * scale_;                                                       \
    if (tid < Ln) h_sh[(NXT) + tid] = bp;                                      \
    __syncthreads();                                                           \
} while(0)

__global__ __launch_bounds__(64,1)
void crf_half(const float* __restrict__ scores,
              const int*   __restrict__ mask,
              const float* __restrict__ trans)
{
    __shared__ float h_sh[2*Ln];
    __shared__ int   m_sh[Tn];

    const int tid = threadIdx.x;
    const int b   = blockIdx.x & (Bn-1);
    const int dir = blockIdx.x >> 6;

    {   // stage mask row (2 KB)
        const int4* msrc = (const int4*)(mask + b * Tn);
        #pragma unroll
        for (int i = tid; i < Tn/4; i += 64) ((int4*)m_sh)[i] = msrc[i];
    }

    const int yy = (tid < Ln) ? tid : 0;
    const float* sp = scores + (size_t)b * Tn * Ln + yy;
    unsigned long long w[24];
    int C2i = 0;

    if (dir == 0) {
        // ---- forward: w = column yy of W = exp(trans) ----
        #pragma unroll
        for (int j = 0; j < 24; j++){
            float wa = ex2f_(trans[(2*j  )*Ln + yy] * LOG2E_F);
            float wb = ex2f_(trans[(2*j+1)*Ln + yy] * LOG2E_F);
            w[j] = pack2_(wa, wb);
        }
        float pf0 = sp[1*Ln], pf1 = sp[2*Ln], pf2 = sp[3*Ln], pf3 = sp[4*Ln];
        float ts = trans[STARTL*Ln + yy];
        float g_prev = ex2f_(ts * LOG2E_F);
        if (tid < Ln) h_sh[tid] = ex2f_((ts + sp[0]) * LOG2E_F);
        __syncthreads();

        for (int t = 0; t < HALF; t += 4){
            STEPF(t  , 0,  Ln, pf0);
            STEPF(t+1, Ln, 0,  pf1);
            STEPF(t+2, 0,  Ln, pf2);
            STEPF(t+3, Ln, 0,  pf3);
        }
        if (tid < Ln) g_scr[0][b][tid] = g_prev;
        if (tid == 0) c_scr[0][b] = C2i;
    } else {
        // ---- backward: w = row yy of W ----
        #pragma unroll
        for (int j = 0; j < 24; j++){
            float wa = ex2f_(trans[yy*Ln + 2*j    ] * LOG2E_F);
            float wb = ex2f_(trans[yy*Ln + 2*j + 1] * LOG2E_F);
            w[j] = pack2_(wa, wb);
        }
        float pf0 = sp[511*Ln], pf1 = sp[510*Ln], pf2 = sp[509*Ln], pf3 = sp[508*Ln];
        // beta_512 = delta_END * 2^-64 (bias compensated by +64 in combine)
        float bp = (yy == ENDL) ? 0x1p-64f : 0.0f;
        if (tid < Ln) h_sh[tid] = bp;
        __syncthreads();

        for (int t = Tn-1; t >= HALF+3; t -= 4){
            STEPB(t  , 0,  Ln, pf0);
            STEPB(t-1, Ln, 0,  pf1);
            STEPB(t-2, 0,  Ln, pf2);
            STEPB(t-3, Ln, 0,  pf3);
        }
        if (tid < Ln) g_scr[1][b][tid] = bp;
        if (tid == 0) c_scr[1][b] = C2i;
    }
}

__global__ __launch_bounds__(64,1)
void crf_combine(const float* __restrict__ scores,
                 const int*   __restrict__ gold_i,   // int32 view (may be int64)
                 const int*   __restrict__ mask,
                 const float* __restrict__ trans,
                 float*       __restrict__ out)
{
    __shared__ float t0_sh[Ln];
    __shared__ float ps[64];
    __shared__ float red[64];
    __shared__ int   miscI[1];

    const int tid = threadIdx.x;
    const int b   = blockIdx.x;

    if (tid < Ln) t0_sh[tid] = trans[tid];
    if (tid == 0){
        int f = 1;
        #pragma unroll
        for (int j = 0; j < 32; j++) f &= (gold_i[2*j+1] == 0);
        miscI[0] = f;
    }
    // Z partial: dot of forward/backward halves
    red[tid] = (tid < Ln) ? g_scr[0][b][tid] * g_scr[1][b][tid] : 0.0f;
    __syncthreads();

    const int is64 = miscI[0];
    const float* sb0 = scores + (size_t)b * Tn * Ln;
    const int*   mb  = mask + b * Tn;
    float p = 0.0f;
    #pragma unroll 4
    for (int tt = tid; tt < Tn; tt += 64){
        int idx = b*Tn + tt;
        int g   = is64 ? gold_i[2*idx] : gold_i[idx];
        p += (float)mb[tt] * (sb0[tt*Ln] + t0_sh[g]);
    }
    ps[tid] = p;
    __syncthreads();

    if (tid == 0){
        float Z = 0.0f;
        #pragma unroll
        for (int i = 0; i < Ln; i++) Z += red[i];
        float tot = 0.0f;
        #pragma unroll
        for (int i = 0; i < 64; i++) tot += ps[i];
        int bias = c_scr[0][b] + c_scr[1][b] - 127*Tn + 64;
        float fsend = ((float)bias + lg2f_(Z)) * LN2_F;
        float res = (fsend - tot - t0_sh[STARTL]) * (1.0f / (float)Bn);
        atomicAdd(out, res);
    }
}

extern "C" void kernel_launch(void* const* d_in, const int* in_sizes, int n_in,
                              void* d_out, int out_size)
{
    const float* scores = (const float*)d_in[0];
    const int*   gold   = (const int*)  d_in[1];
    const int*   mask   = (const int*)  d_in[2];
    const float* trans  = (const float*)d_in[3];
    float* out = (float*)d_out;

    zero_out_k<<<1, 1>>>(out);
    crf_half<<<2*Bn, 64>>>(scores, mask, trans);
    crf_combine<<<Bn, 64>>>(scores, gold, mask, trans, out);
}